// round 6
// baseline (speedup 1.0000x reference)
#include <cuda_runtime.h>
#include <cstdint>

#define N_NODES 100000
#define FEAT 64
#define OUT_DIM 2

// Per-node projected message m = h @ W1  (L2-resident: 800 KB)
__device__ float2 g_m[N_NODES];

// ---------------------------------------------------------------------------
// Fused node kernel (512 threads/block):
//  1) warp-cooperative fold: sW[f] = (W1[f][0], W1[f][1], W2[f][0], W2[f][1])
//     where W1 = W_rel @ W_pred, W2 = W_root @ W_pred (coalesced row loads,
//     butterfly reduce — 16 warps x 8 pairs, fully unrolled)
//  2) thread-per-node projection, NO shuffles:
//     m[i] = h[i] @ W1  (g_m);  out[i] = h[i] @ W2 + bias
// ---------------------------------------------------------------------------
__global__ __launch_bounds__(512)
void node_kernel(const float* __restrict__ pos,
                 const float* __restrict__ vel,
                 const float* __restrict__ W_rel,
                 const float* __restrict__ b_rel,
                 const float* __restrict__ W_root,
                 const float* __restrict__ W_pred,
                 const float* __restrict__ b_pred,
                 float* __restrict__ out) {
    __shared__ float4 sW[FEAT];       // (w1_0, w1_1, w2_0, w2_1) per feature
    __shared__ float  sbias[OUT_DIM];

    int t    = threadIdx.x;
    int warp = t >> 5;                // 0..15
    int lane = t & 31;

    // ---- fold phase: 16 warps x 8 (k,o)-pairs = 128 folded entries ----
    #pragma unroll
    for (int i = 0; i < 8; ++i) {
        int p = warp * 8 + i;         // 0..127
        int k = p >> 1;               // feature row 0..63
        int o = p & 1;                // output col 0..1
        float wp0 = W_pred[lane * OUT_DIM + o];
        float wp1 = W_pred[(lane + 32) * OUT_DIM + o];
        float s1 = W_rel [k * FEAT + lane] * wp0 + W_rel [k * FEAT + lane + 32] * wp1;
        float s2 = W_root[k * FEAT + lane] * wp0 + W_root[k * FEAT + lane + 32] * wp1;
        #pragma unroll
        for (int off = 16; off > 0; off >>= 1) {
            s1 += __shfl_xor_sync(0xffffffffu, s1, off);
            s2 += __shfl_xor_sync(0xffffffffu, s2, off);
        }
        if (lane == 0) {
            float* w = (float*)&sW[k];
            w[o]     = s1;            // .x/.y = W1[k][o]
            w[2 + o] = s2;            // .z/.w = W2[k][o]
        }
    }
    if (warp < OUT_DIM) {             // warps 0,1 compute the bias
        int o = warp;
        float bb = b_rel[lane]      * W_pred[lane * OUT_DIM + o]
                 + b_rel[lane + 32] * W_pred[(lane + 32) * OUT_DIM + o];
        #pragma unroll
        for (int off = 16; off > 0; off >>= 1)
            bb += __shfl_xor_sync(0xffffffffu, bb, off);
        if (lane == 0) sbias[o] = bb + b_pred[o];
    }
    __syncthreads();

    // ---- node phase: one thread per node, float4 loads, smem broadcast ----
    int node = blockIdx.x * 512 + t;
    if (node >= N_NODES) return;

    const float4* pp = (const float4*)(pos + node * 32);
    const float4* vv = (const float4*)(vel + node * 32);

    float m0 = 0.f, m1 = 0.f, r0 = 0.f, r1 = 0.f;
    #pragma unroll
    for (int q = 0; q < 8; ++q) {
        float4 p4 = __ldcs(pp + q);
        float4 v4 = __ldcs(vv + q);
        #pragma unroll
        for (int e = 0; e < 4; ++e) {
            float pe = (&p4.x)[e];
            float ve = (&v4.x)[e];
            float4 wp = sW[q * 4 + e];        // weights for pos feature f
            float4 wv = sW[32 + q * 4 + e];   // weights for vel feature f+32
            m0 += pe * wp.x + ve * wv.x;
            m1 += pe * wp.y + ve * wv.y;
            r0 += pe * wp.z + ve * wv.z;
            r1 += pe * wp.w + ve * wv.w;
        }
    }
    g_m[node] = make_float2(m0, m1);
    ((float2*)out)[node] = make_float2(r0 + sbias[0], r1 + sbias[1]);
}

// ---------------------------------------------------------------------------
// Edge kernel: exactly 2 iterations x 8 edges per thread (balanced, single
// resident wave). out[dst] += m[src] via vector RED (L2 atomics).
// ---------------------------------------------------------------------------
__device__ __forceinline__ void red_v2(float* addr, float2 v) {
    asm volatile("red.global.add.v2.f32 [%0], {%1, %2};"
                 :: "l"(addr), "f"(v.x), "f"(v.y) : "memory");
}

__global__ void edge_kernel(const int* __restrict__ src,
                            const int* __restrict__ dst,
                            float* __restrict__ out,
                            int n_edges) {
    int tid      = blockIdx.x * blockDim.x + threadIdx.x;
    int nthreads = gridDim.x * blockDim.x;

    #pragma unroll
    for (int it = 0; it < 2; ++it) {
        int base = (tid + it * nthreads) * 8;
        if (base + 7 < n_edges) {
            int4 s0 = __ldcs((const int4*)(src + base));
            int4 s1 = __ldcs((const int4*)(src + base + 4));
            int4 d0 = __ldcs((const int4*)(dst + base));
            int4 d1 = __ldcs((const int4*)(dst + base + 4));
            float2 a0 = g_m[s0.x];
            float2 a1 = g_m[s0.y];
            float2 a2 = g_m[s0.z];
            float2 a3 = g_m[s0.w];
            float2 b0 = g_m[s1.x];
            float2 b1 = g_m[s1.y];
            float2 b2 = g_m[s1.z];
            float2 b3 = g_m[s1.w];
            red_v2(out + 2 * d0.x, a0);
            red_v2(out + 2 * d0.y, a1);
            red_v2(out + 2 * d0.z, a2);
            red_v2(out + 2 * d0.w, a3);
            red_v2(out + 2 * d1.x, b0);
            red_v2(out + 2 * d1.y, b1);
            red_v2(out + 2 * d1.z, b2);
            red_v2(out + 2 * d1.w, b3);
        } else if (base < n_edges) {
            for (int i = base; i < n_edges; ++i) {
                float2 mm = g_m[src[i]];
                red_v2(out + 2 * dst[i], mm);
            }
        }
    }
}

// ---------------------------------------------------------------------------
// Launch
// Inputs (metadata order): pos, vel, edge_index, W_rel, b_rel, W_root, W_pred, b_pred
// ---------------------------------------------------------------------------
extern "C" void kernel_launch(void* const* d_in, const int* in_sizes, int n_in,
                              void* d_out, int out_size) {
    const float* pos    = (const float*)d_in[0];
    const float* vel    = (const float*)d_in[1];
    const int*   eidx   = (const int*)  d_in[2];
    const float* W_rel  = (const float*)d_in[3];
    const float* b_rel  = (const float*)d_in[4];
    const float* W_root = (const float*)d_in[5];
    const float* W_pred = (const float*)d_in[6];
    const float* b_pred = (const float*)d_in[7];
    float* out = (float*)d_out;

    const int n_edges = in_sizes[2] / 2;          // 3.2M
    const int* src = eidx;
    const int* dst = eidx + n_edges;

    node_kernel<<<(N_NODES + 511) / 512, 512>>>(pos, vel, W_rel, b_rel, W_root,
                                                W_pred, b_pred, out);

    // 782 blocks x 256 thr = 200,192 threads; x2 iters x8 edges covers 3.2M
    edge_kernel<<<782, 256>>>(src, dst, out, n_edges);
}

// round 7
// speedup vs baseline: 1.0230x; 1.0230x over previous
#include <cuda_runtime.h>
#include <cstdint>

#define N_NODES 100000
#define FEAT 64
#define OUT_DIM 2
#define NBLK 148
#define NTHR 1024

// Per-node projected message m = h @ W1  (L2-resident: 800 KB)
__device__ float2 g_m[N_NODES];
// Grid-barrier counter (epoch-based; never reset, works across graph replays)
__device__ unsigned g_bar = 0;

__device__ __forceinline__ void red_v2(float* addr, float2 v) {
    asm volatile("red.global.add.v2.f32 [%0], {%1, %2};"
                 :: "l"(addr), "f"(v.x), "f"(v.y) : "memory");
}

// ---------------------------------------------------------------------------
// Single persistent kernel: fold -> node projection -> grid barrier -> edges.
// 148 blocks x 1024 threads: grid == SM count, so all blocks are co-resident
// (classic bid%148 placement) and the software grid barrier cannot deadlock.
// ---------------------------------------------------------------------------
__global__ __launch_bounds__(NTHR, 1)
void fused_kernel(const float* __restrict__ pos,
                  const float* __restrict__ vel,
                  const int*   __restrict__ src,
                  const int*   __restrict__ dst,
                  const float* __restrict__ W_rel,
                  const float* __restrict__ b_rel,
                  const float* __restrict__ W_root,
                  const float* __restrict__ W_pred,
                  const float* __restrict__ b_pred,
                  float* __restrict__ out,
                  int n_edges) {
    __shared__ float4 sW[FEAT];       // (W1[f][0], W1[f][1], W2[f][0], W2[f][1])
    __shared__ float  sbias[OUT_DIM];

    int t    = threadIdx.x;
    int warp = t >> 5;                // 0..31
    int lane = t & 31;

    // ---- Phase 1: warp-cooperative weight fold (32 warps x 4 pairs) ----
    #pragma unroll
    for (int i = 0; i < 4; ++i) {
        int p = warp * 4 + i;         // 0..127
        int k = p >> 1;               // feature row 0..63
        int o = p & 1;                // output col 0..1
        float wp0 = W_pred[lane * OUT_DIM + o];
        float wp1 = W_pred[(lane + 32) * OUT_DIM + o];
        float s1 = W_rel [k * FEAT + lane] * wp0 + W_rel [k * FEAT + lane + 32] * wp1;
        float s2 = W_root[k * FEAT + lane] * wp0 + W_root[k * FEAT + lane + 32] * wp1;
        #pragma unroll
        for (int off = 16; off > 0; off >>= 1) {
            s1 += __shfl_xor_sync(0xffffffffu, s1, off);
            s2 += __shfl_xor_sync(0xffffffffu, s2, off);
        }
        if (lane == 0) {
            float* w = (float*)&sW[k];
            w[o]     = s1;
            w[2 + o] = s2;
        }
    }
    if (warp < OUT_DIM) {             // warps 0,1: bias
        int o = warp;
        float bb = b_rel[lane]      * W_pred[lane * OUT_DIM + o]
                 + b_rel[lane + 32] * W_pred[(lane + 32) * OUT_DIM + o];
        #pragma unroll
        for (int off = 16; off > 0; off >>= 1)
            bb += __shfl_xor_sync(0xffffffffu, bb, off);
        if (lane == 0) sbias[o] = bb + b_pred[o];
    }
    __syncthreads();

    // ---- Phase 2: thread-per-node projection (151,552 threads >= 100K) ----
    int node = blockIdx.x * NTHR + t;
    if (node < N_NODES) {
        const float4* pp = (const float4*)(pos + node * 32);
        const float4* vv = (const float4*)(vel + node * 32);
        float m0 = 0.f, m1 = 0.f, r0 = 0.f, r1 = 0.f;
        #pragma unroll
        for (int q = 0; q < 8; ++q) {
            float4 p4 = pp[q];
            float4 v4 = vv[q];
            #pragma unroll
            for (int e = 0; e < 4; ++e) {
                float pe = (&p4.x)[e];
                float ve = (&v4.x)[e];
                float4 wp = sW[q * 4 + e];
                float4 wv = sW[32 + q * 4 + e];
                m0 += pe * wp.x + ve * wv.x;
                m1 += pe * wp.y + ve * wv.y;
                r0 += pe * wp.z + ve * wv.z;
                r1 += pe * wp.w + ve * wv.w;
            }
        }
        g_m[node] = make_float2(m0, m1);
        ((float2*)out)[node] = make_float2(r0 + sbias[0], r1 + sbias[1]);
    }

    // ---- Grid barrier (epoch-based, replay-safe) ----
    __threadfence();                  // release: g_m / out visible gpu-wide
    __syncthreads();
    if (t == 0) {
        unsigned my = atomicAdd(&g_bar, 1u);
        unsigned target = (my / (unsigned)gridDim.x + 1u) * (unsigned)gridDim.x;
        while (atomicAdd(&g_bar, 0u) < target) { }
        __threadfence();              // acquire
    }
    __syncthreads();

    // ---- Phase 3: edge scatter, grid-stride 8-edge chunks ----
    int tid = blockIdx.x * NTHR + t;
    const int NT = NBLK * NTHR;
    int n8 = n_edges & ~7;
    for (int base = tid * 8; base < n8; base += NT * 8) {
        int4 s0 = __ldcs((const int4*)(src + base));
        int4 s1 = __ldcs((const int4*)(src + base + 4));
        int4 d0 = __ldcs((const int4*)(dst + base));
        int4 d1 = __ldcs((const int4*)(dst + base + 4));
        float2 a0 = g_m[s0.x];
        float2 a1 = g_m[s0.y];
        float2 a2 = g_m[s0.z];
        float2 a3 = g_m[s0.w];
        float2 b0 = g_m[s1.x];
        float2 b1 = g_m[s1.y];
        float2 b2 = g_m[s1.z];
        float2 b3 = g_m[s1.w];
        red_v2(out + 2 * d0.x, a0);
        red_v2(out + 2 * d0.y, a1);
        red_v2(out + 2 * d0.z, a2);
        red_v2(out + 2 * d0.w, a3);
        red_v2(out + 2 * d1.x, b0);
        red_v2(out + 2 * d1.y, b1);
        red_v2(out + 2 * d1.z, b2);
        red_v2(out + 2 * d1.w, b3);
    }
    if (tid == 0) {                   // tail (<8 edges; n_edges=3.2M -> empty)
        for (int i = n8; i < n_edges; ++i) {
            float2 mm = g_m[src[i]];
            red_v2(out + 2 * dst[i], mm);
        }
    }
}

// ---------------------------------------------------------------------------
// Launch
// Inputs (metadata order): pos, vel, edge_index, W_rel, b_rel, W_root, W_pred, b_pred
// ---------------------------------------------------------------------------
extern "C" void kernel_launch(void* const* d_in, const int* in_sizes, int n_in,
                              void* d_out, int out_size) {
    const float* pos    = (const float*)d_in[0];
    const float* vel    = (const float*)d_in[1];
    const int*   eidx   = (const int*)  d_in[2];
    const float* W_rel  = (const float*)d_in[3];
    const float* b_rel  = (const float*)d_in[4];
    const float* W_root = (const float*)d_in[5];
    const float* W_pred = (const float*)d_in[6];
    const float* b_pred = (const float*)d_in[7];
    float* out = (float*)d_out;

    const int n_edges = in_sizes[2] / 2;          // 3.2M
    const int* src = eidx;
    const int* dst = eidx + n_edges;

    fused_kernel<<<NBLK, NTHR>>>(pos, vel, src, dst,
                                 W_rel, b_rel, W_root, W_pred, b_pred,
                                 out, n_edges);
}